// round 6
// baseline (speedup 1.0000x reference)
#include <cuda_runtime.h>

#define D 32
#define NMID 80
#define NLAY 82            // total layers
#define ST 36              // padded row stride (floats); cols 0..31=A, 32=c
#define MSZ (D * ST)       // 1152 floats = 4.5 KB per (A|c) tile
#define NBA 14             // compose phase-A blocks
#define CH  6              // layers per phase-A block (last gets 4)
#define NBB 4              // compose phase-B blocks
#define NBLK 148           // one block per SM -> guaranteed co-resident
#define NT  512            // threads per block (288 active in mm)
#define NACT 288           // 32 rows x 9 col-groups

// Global scratch (no allocations allowed).
__device__ __align__(16) float gP[NBA * MSZ];   // phase-A partials
__device__ __align__(16) float gQ[NBB * MSZ];   // phase-B partials
__device__ __align__(16) float gF[MSZ];         // final composed (A|c)
__device__ int gFlag;                            // 1 => A negligible
__device__ unsigned gCount = 0;                  // barrier counter (self-reset)
__device__ volatile unsigned gPhase = 0;         // monotone phase (replay-safe)

// ---------------------------------------------------------------------------
// Grid barrier across all NBLK co-resident blocks (1 block/SM). gPhase is
// monotone across graph replays; base captured at entry is uniform because
// no block can pass barrier 1 until every block has entered and read it.
// ---------------------------------------------------------------------------
__device__ __forceinline__ void grid_barrier(unsigned base, int it) {
    __syncthreads();
    if (threadIdx.x == 0) {
        __threadfence();
        unsigned c = atomicAdd(&gCount, 1u);
        if (c == NBLK - 1u) {
            gCount = 0u;
            __threadfence();
            gPhase = gPhase + 1u;           // single writer (last arriver)
        } else {
            const unsigned tgt = base + (unsigned)it;
            while (gPhase < tgt) { __nanosleep(32); }
        }
        __threadfence();
    }
    __syncthreads();
}

// ---------------------------------------------------------------------------
// Build (W|b) tile in smem, vectorized. S is [32 x ST] floats.
// Threads 0..255: A-part (8 float4 per row). Threads 256..287: col group 8
// (= {b[r],0,0,0}).
// ---------------------------------------------------------------------------
__device__ __forceinline__ void load_aug(float* S, const float* __restrict__ W,
                                         const float* __restrict__ b) {
    const int t = threadIdx.x;
    float4* S4 = (float4*)S;
    if (t < 256) {
        const int r = t >> 3, q = t & 7;
        S4[r * 9 + q] = ((const float4*)W)[r * 8 + q];
    } else if (t < NACT) {
        const int r = t - 256;
        S4[r * 9 + 8] = make_float4(b[r], 0.f, 0.f, 0.f);
    }
}

// global <-> smem tile copies: one float4 per active thread (288*4 = 1152).
__device__ __forceinline__ void load_mat(float* S, const float* g) {
    if (threadIdx.x < NACT)
        ((float4*)S)[threadIdx.x] = ((const float4*)g)[threadIdx.x];
}
__device__ __forceinline__ void store_mat(float* g, const float* S) {
    if (threadIdx.x < NACT)
        ((float4*)g)[threadIdx.x] = ((const float4*)S)[threadIdx.x];
}

// ---------------------------------------------------------------------------
// Affine compose: OUT = L o R (apply R first):
//   OUT.A = L.A * R.A ; OUT.c = L.A * R.c + L.c
// Thread (r,g) computes OUT[r][4g..4g+3]; col group 8 holds c in .x.
// ---------------------------------------------------------------------------
__device__ __forceinline__ float4 mm_val(const float* __restrict__ Ls,
                                         const float* __restrict__ Rs,
                                         int r, int g) {
    const float4* L4 = (const float4*)(Ls + r * ST);
    const float4* R4 = (const float4*)Rs;
    float4 a = make_float4(0.f, 0.f, 0.f, 0.f);
#pragma unroll
    for (int k4 = 0; k4 < 8; ++k4) {
        const float4 lv = L4[k4];
        const float4 r0 = R4[(4 * k4 + 0) * 9 + g];
        const float4 r1 = R4[(4 * k4 + 1) * 9 + g];
        const float4 r2 = R4[(4 * k4 + 2) * 9 + g];
        const float4 r3 = R4[(4 * k4 + 3) * 9 + g];
        a.x = fmaf(lv.x, r0.x, a.x); a.y = fmaf(lv.x, r0.y, a.y);
        a.z = fmaf(lv.x, r0.z, a.z); a.w = fmaf(lv.x, r0.w, a.w);
        a.x = fmaf(lv.y, r1.x, a.x); a.y = fmaf(lv.y, r1.y, a.y);
        a.z = fmaf(lv.y, r1.z, a.z); a.w = fmaf(lv.y, r1.w, a.w);
        a.x = fmaf(lv.z, r2.x, a.x); a.y = fmaf(lv.z, r2.y, a.y);
        a.z = fmaf(lv.z, r2.z, a.z); a.w = fmaf(lv.z, r2.w, a.w);
        a.x = fmaf(lv.w, r3.x, a.x); a.y = fmaf(lv.w, r3.y, a.y);
        a.z = fmaf(lv.w, r3.z, a.z); a.w = fmaf(lv.w, r3.w, a.w);
    }
    if (g == 8) a.x += Ls[r * ST + D];     // + L.c
    return a;
}

__device__ __forceinline__ void mm(const float* Ls, const float* Rs,
                                   float* out, int r, int g) {
    if (threadIdx.x < NACT) {
        float4 a = mm_val(Ls, Rs, r, g);
        ((float4*)out)[r * 9 + g] = a;
    }
}

// Serial right-to-left chain over tiles S[0..n-1] (larger i = later layer).
// Uses S[6] as temp, recycles consumed slots. Returns result slot index.
__device__ __forceinline__ int chain(float* Sb, int n, int r, int g) {
#define TILE(i) (Sb + (i) * MSZ)
    __syncthreads();
    mm(TILE(1), TILE(0), TILE(6), r, g);
    int prev = 6;
    for (int i = 2; i < n; ++i) {
        __syncthreads();
        mm(TILE(i), TILE(prev), TILE(i - 2), r, g);
        prev = i - 2;
    }
    __syncthreads();
    return prev;
#undef TILE
}

// ---------------------------------------------------------------------------
// Fused kernel: compose (blocks 0..13, 3 barriers) then all 148 blocks
// stream the output.
// ---------------------------------------------------------------------------
__global__ void __launch_bounds__(NT)
fused_kernel(const float* __restrict__ W1, const float* __restrict__ b1,
             const float* __restrict__ Wm, const float* __restrict__ bm,
             const float* __restrict__ W6, const float* __restrict__ b6,
             const float* __restrict__ x, float* __restrict__ out, int n4) {
    __shared__ __align__(16) float S[7 * MSZ];   // 31.5 KB
    const unsigned base = gPhase;
    const int k = blockIdx.x;
    const int t = threadIdx.x;
    const int r = t / 9, g = t % 9;              // valid for t < NACT

    // ---- Phase A: 14 blocks x up-to-6 layers ----
    if (k < NBA) {
        const int lo = k * CH;
        const int hi = (lo + CH < NLAY) ? lo + CH : NLAY;
        const int n  = hi - lo;                   // 6 (last block: 4)
        for (int i = 0; i < n; ++i) {
            const int l = lo + i;
            const float* W; const float* b;
            if (l == 0)             { W = W1; b = b1; }
            else if (l == NLAY - 1) { W = W6; b = b6; }
            else { W = Wm + (size_t)(l - 1) * D * D; b = bm + (l - 1) * D; }
            load_aug(S + i * MSZ, W, b);
        }
        int res = chain(S, n, r, g);
        store_mat(gP + (size_t)k * MSZ, S + res * MSZ);
    }
    grid_barrier(base, 1);

    // ---- Phase B: 4 blocks combine the 14 partials ----
    if (k < NBB) {
        const int lo = k * 4;
        const int hi = (lo + 4 < NBA) ? lo + 4 : NBA;
        const int n  = hi - lo;                   // 4,4,4,2
        for (int i = 0; i < n; ++i)
            load_mat(S + i * MSZ, gP + (size_t)(lo + i) * MSZ);
        int res = chain(S, n, r, g);
        store_mat(gQ + (size_t)k * MSZ, S + res * MSZ);
    }
    grid_barrier(base, 2);

    // ---- Phase C: block 0 combines 4 -> gF + flag ----
    if (k == 0) {
        for (int i = 0; i < NBB; ++i)
            load_mat(S + i * MSZ, gQ + (size_t)i * MSZ);
        __syncthreads();
        mm(S + 1 * MSZ, S + 0 * MSZ, S + 6 * MSZ, r, g);   // P1 o P0
        __syncthreads();
        mm(S + 2 * MSZ, S + 6 * MSZ, S + 0 * MSZ, r, g);   // P2 o ...
        __syncthreads();
        __shared__ int samax;
        if (t == 0) samax = 0;
        __syncthreads();
        if (t < NACT) {
            float4 a = mm_val(S + 3 * MSZ, S + 0 * MSZ, r, g);  // P3 o ...
            ((float4*)gF)[r * 9 + g] = a;
            float m = 0.f;
            if (g < 8)
                m = fmaxf(fmaxf(fabsf(a.x), fabsf(a.y)),
                          fmaxf(fabsf(a.z), fabsf(a.w)));
#pragma unroll
            for (int o = 16; o > 0; o >>= 1)
                m = fmaxf(m, __shfl_xor_sync(0xffffffffu, m, o));
            if ((t & 31) == 0) atomicMax(&samax, __float_as_int(m));
        }
        __syncthreads();
        if (t == 0)
            gFlag = (__int_as_float(samax) < 1e-12f) ? 1 : 0;
    }
    grid_barrier(base, 3);

    // ---- Output: all 148 blocks stream ----
    const int tid = k * NT + t;
    const int nt  = NBLK * NT;                // 75776, multiple of 8
    const int flag = gFlag;

    if (flag) {
        const int slot = tid & 7;
        float4 cv = make_float4(gF[(slot * 4 + 0) * ST + D],
                                gF[(slot * 4 + 1) * ST + D],
                                gF[(slot * 4 + 2) * ST + D],
                                gF[(slot * 4 + 3) * ST + D]);
        float4* o4 = (float4*)out;
#pragma unroll 4
        for (int i = tid; i < n4; i += nt) __stcs(&o4[i], cv);
    } else {
        const int n = n4 * 4;
        for (int e = tid; e < n; e += nt) {
            const int b = e >> 5;
            const int i = e & 31;
            const float* xr = x + (size_t)b * D;
            float acc = gF[i * ST + D];
#pragma unroll
            for (int jj = 0; jj < D; ++jj)
                acc = fmaf(gF[i * ST + jj], xr[jj], acc);
            out[e] = acc;
        }
    }
}

// ---------------------------------------------------------------------------
// Launch. Inputs identified by element counts (relative order disambiguates
// W1/W6 and b1/b6).
// ---------------------------------------------------------------------------
extern "C" void kernel_launch(void* const* d_in, const int* in_sizes, int n_in,
                              void* d_out, int out_size) {
    const float *x = 0, *W1 = 0, *b1 = 0, *Wm = 0, *bm = 0, *W6 = 0, *b6 = 0;
    for (int i = 0; i < n_in; ++i) {
        const int s = in_sizes[i];
        const float* p = (const float*)d_in[i];
        if (s == NMID * D * D) {
            Wm = p;
        } else if (s > 100000) {
            x = p;
        } else if (s == NMID * D) {
            bm = p;
        } else if (s == D * D) {
            if (!W1) W1 = p; else W6 = p;
        } else if (s == D) {
            if (!b1) b1 = p; else b6 = p;
        }
    }

    const int n4 = out_size / 4;
    fused_kernel<<<NBLK, NT>>>(W1, b1, Wm, bm, W6, b6, x, (float*)d_out, n4);
}

// round 7
// speedup vs baseline: 1.0384x; 1.0384x over previous
#include <cuda_runtime.h>

#define D 32
#define NMID 80
#define NLAY 82            // total layers
#define ST 36              // padded row stride; cols 0..31 = A, 32 = c
#define MSZ (D * ST)       // 1152 floats = 4.5 KB per (A|c) tile
#define NBA 14             // phase-A blocks (6 layers each; last: 4)
#define NBB 4              // phase-B blocks
#define NBLK 148           // 1 block/SM -> guaranteed co-resident
#define NT  864            // 27 warps = 3 groups x 288 threads
#define NACT 288           // threads per mm group (32 rows x 9 col-groups)

// Global scratch (no allocations allowed).
__device__ __align__(16) float gP[NBA * MSZ];
__device__ __align__(16) float gQ[NBB * MSZ];
__device__ __align__(16) float gF[MSZ];
__device__ int gFlag;
__device__ unsigned gCount = 0;
__device__ volatile unsigned gPhase = 0;   // monotone (graph-replay-safe)

// ---------------------------------------------------------------------------
// Grid barrier across NBLK co-resident blocks (1/SM).
// ---------------------------------------------------------------------------
__device__ __forceinline__ void grid_barrier(unsigned base, int it) {
    __syncthreads();
    if (threadIdx.x == 0) {
        __threadfence();
        unsigned c = atomicAdd(&gCount, 1u);
        if (c == NBLK - 1u) {
            gCount = 0u;
            __threadfence();
            gPhase = gPhase + 1u;          // single writer (last arriver)
        } else {
            const unsigned tgt = base + (unsigned)it;
            while (gPhase < tgt) { __nanosleep(32); }
        }
        __threadfence();
    }
    __syncthreads();
}

// ---------------------------------------------------------------------------
// OUT = L o R (apply R first): OUT.A = L.A*R.A ; OUT.c = L.A*R.c + L.c.
// One GROUP of 288 threads; tt in [0,288): r = tt/9, g = tt%9 computes
// OUT[r][4g..4g+3]; col-group 8 holds c in .x (cols 33..35 stay zero).
// ---------------------------------------------------------------------------
__device__ __forceinline__ float4 mm_val(const float* __restrict__ Ls,
                                         const float* __restrict__ Rs,
                                         int r, int g) {
    const float4* L4 = (const float4*)(Ls + r * ST);
    const float4* R4 = (const float4*)Rs;
    float4 a = make_float4(0.f, 0.f, 0.f, 0.f);
#pragma unroll
    for (int k4 = 0; k4 < 8; ++k4) {
        const float4 lv = L4[k4];
        const float4 r0 = R4[(4 * k4 + 0) * 9 + g];
        const float4 r1 = R4[(4 * k4 + 1) * 9 + g];
        const float4 r2 = R4[(4 * k4 + 2) * 9 + g];
        const float4 r3 = R4[(4 * k4 + 3) * 9 + g];
        a.x = fmaf(lv.x, r0.x, a.x); a.y = fmaf(lv.x, r0.y, a.y);
        a.z = fmaf(lv.x, r0.z, a.z); a.w = fmaf(lv.x, r0.w, a.w);
        a.x = fmaf(lv.y, r1.x, a.x); a.y = fmaf(lv.y, r1.y, a.y);
        a.z = fmaf(lv.y, r1.z, a.z); a.w = fmaf(lv.y, r1.w, a.w);
        a.x = fmaf(lv.z, r2.x, a.x); a.y = fmaf(lv.z, r2.y, a.y);
        a.z = fmaf(lv.z, r2.z, a.z); a.w = fmaf(lv.z, r2.w, a.w);
        a.x = fmaf(lv.w, r3.x, a.x); a.y = fmaf(lv.w, r3.y, a.y);
        a.z = fmaf(lv.w, r3.z, a.z); a.w = fmaf(lv.w, r3.w, a.w);
    }
    if (g == 8) a.x += Ls[r * ST + D];
    return a;
}

__device__ __forceinline__ void mm_g(const float* Ls, const float* Rs,
                                     float* out, int tt) {
    const int r = tt / 9, g = tt % 9;
    ((float4*)out)[tt] = mm_val(Ls, Rs, r, g);
}

// Layer pointer helpers.
struct LayPtr { const float* W; const float* b; };
__device__ __forceinline__ LayPtr layer_ptr(int l,
        const float* W1, const float* b1, const float* Wm, const float* bm,
        const float* W6, const float* b6) {
    LayPtr p;
    if (l == 0)             { p.W = W1; p.b = b1; }
    else if (l == NLAY - 1) { p.W = W6; p.b = b6; }
    else { p.W = Wm + (size_t)(l - 1) * D * D; p.b = bm + (l - 1) * D; }
    return p;
}

// ---------------------------------------------------------------------------
// Fused kernel.
// ---------------------------------------------------------------------------
__global__ void __launch_bounds__(NT)
fused_kernel(const float* __restrict__ W1, const float* __restrict__ b1,
             const float* __restrict__ Wm, const float* __restrict__ bm,
             const float* __restrict__ W6, const float* __restrict__ b6,
             const float* __restrict__ x, float* __restrict__ out, int n4) {
    __shared__ __align__(16) float S[9 * MSZ];   // 40.5 KB
    const unsigned base = gPhase;
    const int k = blockIdx.x;
    const int t = threadIdx.x;
    const int grp = t / NACT;          // 0,1,2
    const int tt  = t % NACT;

    // ---- Phase A: 14 blocks, up-to-6 layers each, depth-3 tree ----
    if (k < NBA) {
        const int lo = k * 6;
        const int n  = (NLAY - lo < 6) ? (NLAY - lo) : 6;   // 6 (last: 4)

        // Parallel tile loads: A-parts by t<768, biases by t>=768.
        if (t < 768) {
            const int tile0 = t >> 8;            // 0..2
            const int i = t & 255;
            const int r = i >> 3, q = i & 7;
            for (int tile = tile0; tile < n; tile += 3) {
                LayPtr p = layer_ptr(lo + tile, W1, b1, Wm, bm, W6, b6);
                ((float4*)(S + tile * MSZ))[r * 9 + q] =
                    ((const float4*)p.W)[r * 8 + q];
            }
        } else {
            const int j0 = t - 768;              // 0..95
            for (int j = j0; j < n * 32; j += 96) {
                const int tile = j >> 5, r = j & 31;
                LayPtr p = layer_ptr(lo + tile, W1, b1, Wm, bm, W6, b6);
                ((float4*)(S + tile * MSZ))[r * 9 + 8] =
                    make_float4(p.b[r], 0.f, 0.f, 0.f);
            }
        }
        __syncthreads();

        // Level 1: up to 3 independent pair-products.
        if (grp == 0)               mm_g(S + 1 * MSZ, S + 0 * MSZ, S + 6 * MSZ, tt);
        else if (grp == 1)          mm_g(S + 3 * MSZ, S + 2 * MSZ, S + 7 * MSZ, tt);
        else if (grp == 2 && n > 4) mm_g(S + 5 * MSZ, S + 4 * MSZ, S + 8 * MSZ, tt);
        __syncthreads();
        // Level 2: T23 o T01.
        if (grp == 0) mm_g(S + 7 * MSZ, S + 6 * MSZ, S + 0 * MSZ, tt);
        __syncthreads();
        // Level 3 (only when n == 6): T45 o (T23 o T01).
        int res = 0;
        if (n == 6) {
            if (grp == 0) mm_g(S + 8 * MSZ, S + 0 * MSZ, S + 1 * MSZ, tt);
            res = 1;
        }
        __syncthreads();
        if (t < NACT)
            ((float4*)(gP + (size_t)k * MSZ))[t] = ((float4*)(S + res * MSZ))[t];
    }
    grid_barrier(base, 1);

    // ---- Phase B: 4 blocks combine 14 partials (4,4,4,2), depth-2 tree ----
    if (k < NBB) {
        const int lo = k * 4;
        const int n  = (NBA - lo < 4) ? (NBA - lo) : 4;     // 4,4,4,2
        for (int j = t; j < n * NACT; j += NT) {
            const int tile = j / NACT, idx = j % NACT;
            ((float4*)(S + tile * MSZ))[idx] =
                ((const float4*)(gP + (size_t)(lo + tile) * MSZ))[idx];
        }
        __syncthreads();
        int res;
        if (n == 4) {
            if (grp == 0)      mm_g(S + 1 * MSZ, S + 0 * MSZ, S + 4 * MSZ, tt);
            else if (grp == 1) mm_g(S + 3 * MSZ, S + 2 * MSZ, S + 5 * MSZ, tt);
            __syncthreads();
            if (grp == 0) mm_g(S + 5 * MSZ, S + 4 * MSZ, S + 0 * MSZ, tt);
            res = 0;
        } else {  // n == 2
            if (grp == 0) mm_g(S + 1 * MSZ, S + 0 * MSZ, S + 4 * MSZ, tt);
            res = 4;
        }
        __syncthreads();
        if (t < NACT)
            ((float4*)(gQ + (size_t)k * MSZ))[t] = ((float4*)(S + res * MSZ))[t];
    }
    grid_barrier(base, 2);

    // ---- Phase C: block 0 combines 4 -> gF + flag, depth-2 tree ----
    __shared__ int samax;
    if (k == 0) {
        for (int j = t; j < NBB * NACT; j += NT) {
            const int tile = j / NACT, idx = j % NACT;
            ((float4*)(S + tile * MSZ))[idx] =
                ((const float4*)(gQ + (size_t)tile * MSZ))[idx];
        }
        __syncthreads();
        if (grp == 0)      mm_g(S + 1 * MSZ, S + 0 * MSZ, S + 4 * MSZ, tt);
        else if (grp == 1) mm_g(S + 3 * MSZ, S + 2 * MSZ, S + 5 * MSZ, tt);
        if (t == 0) samax = 0;
        __syncthreads();
        if (grp == 0) {
            const int r = tt / 9, g = tt % 9;
            float4 a = mm_val(S + 5 * MSZ, S + 4 * MSZ, r, g);
            ((float4*)gF)[tt] = a;
            float m = 0.f;
            if (g < 8)
                m = fmaxf(fmaxf(fabsf(a.x), fabsf(a.y)),
                          fmaxf(fabsf(a.z), fabsf(a.w)));
#pragma unroll
            for (int o = 16; o > 0; o >>= 1)
                m = fmaxf(m, __shfl_xor_sync(0xffffffffu, m, o));
            if ((tt & 31) == 0) atomicMax(&samax, __float_as_int(m));
        }
        __syncthreads();
        if (t == 0)
            gFlag = (__int_as_float(samax) < 1e-12f) ? 1 : 0;
    }
    grid_barrier(base, 3);

    // ---- Output: all 148 blocks stream ----
    const int tid = k * NT + t;
    const int nt  = NBLK * NT;               // 127872, multiple of 8
    const int flag = gFlag;

    if (flag) {
        const int slot = tid & 7;
        float4 cv = make_float4(gF[(slot * 4 + 0) * ST + D],
                                gF[(slot * 4 + 1) * ST + D],
                                gF[(slot * 4 + 2) * ST + D],
                                gF[(slot * 4 + 3) * ST + D]);
        float4* o4 = (float4*)out;
#pragma unroll 4
        for (int i = tid; i < n4; i += nt) __stcs(&o4[i], cv);
    } else {
        const int n = n4 * 4;
        for (int e = tid; e < n; e += nt) {
            const int b = e >> 5;
            const int i = e & 31;
            const float* xr = x + (size_t)b * D;
            float acc = gF[i * ST + D];
#pragma unroll
            for (int jj = 0; jj < D; ++jj)
                acc = fmaf(gF[i * ST + jj], xr[jj], acc);
            out[e] = acc;
        }
    }
}

// ---------------------------------------------------------------------------
// Launch. Inputs identified by element counts (relative order disambiguates
// W1/W6 and b1/b6).
// ---------------------------------------------------------------------------
extern "C" void kernel_launch(void* const* d_in, const int* in_sizes, int n_in,
                              void* d_out, int out_size) {
    const float *x = 0, *W1 = 0, *b1 = 0, *Wm = 0, *bm = 0, *W6 = 0, *b6 = 0;
    for (int i = 0; i < n_in; ++i) {
        const int s = in_sizes[i];
        const float* p = (const float*)d_in[i];
        if (s == NMID * D * D) {
            Wm = p;
        } else if (s > 100000) {
            x = p;
        } else if (s == NMID * D) {
            bm = p;
        } else if (s == D * D) {
            if (!W1) W1 = p; else W6 = p;
        } else if (s == D) {
            if (!b1) b1 = p; else b6 = p;
        }
    }

    const int n4 = out_size / 4;
    fused_kernel<<<NBLK, NT>>>(W1, b1, Wm, bm, W6, b6, x, (float*)d_out, n4);
}